// round 9
// baseline (speedup 1.0000x reference)
#include <cuda_runtime.h>
#include <cstdint>

// Shapes (fixed by the problem)
#define B 8
#define N 256
#define IN 64
#define F 64          // H*D
#define H 8
#define D 8
#define RPC 4         // rows (i values) per CTA in the attention kernel

#define L2E 1.4426950408889634f
#define M2C (20.0f * 1.4426950408889634f)   // fixed softmax shift (log2 domain)

typedef unsigned long long ull;

// ---- packed f32x2 helpers (sm_103a FFMA2/FADD2 only reachable via PTX) ----
__device__ __forceinline__ ull pack2(float lo, float hi) {
    ull r; asm("mov.b64 %0, {%1, %2};" : "=l"(r) : "f"(lo), "f"(hi)); return r;
}
__device__ __forceinline__ void unpack2(ull v, float& lo, float& hi) {
    asm("mov.b64 {%0, %1}, %2;" : "=f"(lo), "=f"(hi) : "l"(v));
}
__device__ __forceinline__ ull fma2(ull a, ull b, ull c) {
    ull d; asm("fma.rn.f32x2 %0, %1, %2, %3;" : "=l"(d) : "l"(a), "l"(b), "l"(c)); return d;
}
__device__ __forceinline__ ull add2(ull a, ull b) {
    ull d; asm("add.rn.f32x2 %0, %1, %2;" : "=l"(d) : "l"(a), "l"(b)); return d;
}
__device__ __forceinline__ float ex2(float x) {
    float y; asm("ex2.approx.ftz.f32 %0, %1;" : "=f"(y) : "f"(x)); return y;
}

// Scratch (allocation-free rule: __device__ globals)
__device__ float g_Q[B * N * F];
__device__ float g_K[B * N * F];   // pre-scaled by D^-0.5
__device__ float g_V[B * N * F];

// ---------------------------------------------------------------------------
// Kernel A: Q/K/V projections.  grid = B*N/4 = 512 blocks, 256 threads.
// ---------------------------------------------------------------------------
__global__ void __launch_bounds__(256) qkv_kernel(
    const float* __restrict__ h,
    const float* __restrict__ Wq,
    const float* __restrict__ Wk,
    const float* __restrict__ Wv)
{
    __shared__ float hs[4][IN];
    int r   = threadIdx.x >> 6;    // 0..3
    int f   = threadIdx.x & 63;    // 0..63
    int row = blockIdx.x * 4 + r;

    hs[r][f] = h[row * IN + f];
    __syncthreads();

    float aq = 0.f, ak = 0.f, av = 0.f;
#pragma unroll
    for (int k = 0; k < IN; k++) {
        float hv = hs[r][k];
        aq = fmaf(hv, Wq[k * F + f], aq);
        ak = fmaf(hv, Wk[k * F + f], ak);
        av = fmaf(hv, Wv[k * F + f], av);
    }
    g_Q[row * F + f] = aq;
    g_K[row * F + f] = ak * 0.35355339059327373f;  // D^-0.5
    g_V[row * F + f] = av;
}

// ---------------------------------------------------------------------------
// Kernel B: fused qk + softmax(fixed-shift M=20, exact) + weighted sum.
// grid = B*(N/RPC) = 512 blocks, 256 threads (8 warps), 3 CTAs/SM (reg room).
// Warp pair (2w, 2w+1) shares row r=w, splitting j into halves of 128.
// Lanes: jo = lane>>4 (which of 2 j's per step), q = lane&15 owns float4
// slice [4q,4q+4) of the f dim, h = q>>1.
// Phase 3: depth-3 register pipeline on e_att/e_value (DRAM), depth-2 on V (L2).
// ---------------------------------------------------------------------------
__global__ void __launch_bounds__(256, 3) attn_kernel(
    const float* __restrict__ e_att,
    const float* __restrict__ e_value,
    const uint32_t* __restrict__ attn_mask,   // 4-byte elems; true <=> nonzero
    float* __restrict__ out)
{
    __shared__ float qk_s[RPC][N][H];    // 32 KB; qk*L2E - M2, or -1e30 masked
    __shared__ float q_s[RPC][F];        // 1 KB
    __shared__ float msk_s[RPC][N];      // 4 KB (phase-1 only)
    __shared__ float part[8][32][9];     // 9 KB (padded): l0..3, a0..3

    const int blk  = blockIdx.x;
    const int b    = blk >> 6;           // 64 blocks per batch
    const int i0   = (blk & 63) * RPC;
    const int tid  = threadIdx.x;
    const int wid  = tid >> 5;           // 0..7
    const int lane = tid & 31;

    // ---- load Q rows + mask into smem ----
    for (int t = tid; t < RPC * F; t += 256) {
        int r = t >> 6, f = t & 63;
        q_s[r][f] = g_Q[(b * N + i0 + r) * F + f];
    }
    for (int t = tid; t < RPC * N; t += 256) {
        int r = t >> 8, j = t & 255;
        msk_s[r][j] = (attn_mask[(b * N + i0 + r) * N + j] != 0u) ? 1.0f : 0.0f;
    }
    __syncthreads();

    // ---- phase 1: qk_s[r][j][h] = mask ? dot8*L2E - M2 : -1e30 ----
    {
        const int h  = lane >> 2;        // 0..7
        const int jm = lane & 3;         // 0..3
        float qreg[RPC][8];
#pragma unroll
        for (int r = 0; r < RPC; r++)
#pragma unroll
            for (int d = 0; d < 8; d++)
                qreg[r][d] = q_s[r][h * 8 + d];

        const float4* Kb = (const float4*)(g_K + b * N * F);
        for (int jg = wid * 8; jg < wid * 8 + 8; jg++) {
            int j = jm + 4 * jg;
            float4 k0 = Kb[j * 16 + h * 2];
            float4 k1 = Kb[j * 16 + h * 2 + 1];
#pragma unroll
            for (int r = 0; r < RPC; r++) {
                float s = qreg[r][0] * k0.x;
                s = fmaf(qreg[r][1], k0.y, s);
                s = fmaf(qreg[r][2], k0.z, s);
                s = fmaf(qreg[r][3], k0.w, s);
                s = fmaf(qreg[r][4], k1.x, s);
                s = fmaf(qreg[r][5], k1.y, s);
                s = fmaf(qreg[r][6], k1.z, s);
                s = fmaf(qreg[r][7], k1.w, s);
                qk_s[r][j][h] = (msk_s[r][j] != 0.0f) ? fmaf(s, L2E, -M2C)
                                                      : -1e30f;
            }
        }
    }
    __syncthreads();

    // ---- phase 3: streaming softmax + weighted accumulation ----
    {
        const int r     = wid >> 1;
        const int jhalf = wid & 1;
        const int i     = i0 + r;
        const int jo    = lane >> 4;     // 0/1
        const int q     = lane & 15;     // float4 index in f dim
        const int h     = q >> 1;
        const int j0    = jhalf * 128;

        const ulonglong2* pea = (const ulonglong2*)(e_att   + (size_t)(b * N + i) * N * F);
        const ulonglong2* pev = (const ulonglong2*)(e_value + (size_t)(b * N + i) * N * F);
        const ulonglong2* pV  = (const ulonglong2*)(g_V + b * N * F);

        const ull L2E2 = pack2(L2E, L2E);

        ull L01 = 0ull, L23 = 0ull, A01 = 0ull, A23 = 0ull;

        const int idx0   = (j0 + jo) * 16 + q;
        const int idxmax = idx0 + 63 * 32;

        // prime the pipeline: EA/EV slots k, k+1, k+2 ; VV slots k, k+1
        ulonglong2 EA0 = pea[idx0],      EV0 = pev[idx0];
        ulonglong2 EA1 = pea[idx0 + 32], EV1 = pev[idx0 + 32];
        ulonglong2 EA2 = pea[idx0 + 64], EV2 = pev[idx0 + 64];
        ulonglong2 VV0 = pV[idx0];
        ulonglong2 VV1 = pV[idx0 + 32];

        int idx = idx0;
#pragma unroll 2
        for (int k = 0; k < 64; k++) {
            // prefetch k+3 for DRAM streams, k+2 for V (clamped, in-bounds)
            int idp3 = idx + 96;  idp3 = (idp3 <= idxmax) ? idp3 : idxmax;
            int idp2 = idx + 64;  idp2 = (idp2 <= idxmax) ? idp2 : idxmax;
            ulonglong2 EA3 = pea[idp3];
            ulonglong2 EV3 = pev[idp3];
            ulonglong2 VV2 = pV[idp2];

            float qk  = qk_s[r][j0 + 2 * k + jo][h];
            ull   qk2 = pack2(qk, qk);

            ull t01 = fma2(EA0.x, L2E2, qk2);
            ull t23 = fma2(EA0.y, L2E2, qk2);
            float f0, f1, f2, f3;
            unpack2(t01, f0, f1);
            unpack2(t23, f2, f3);
            float p0 = ex2(f0), p1 = ex2(f1), p2 = ex2(f2), p3 = ex2(f3);
            ull p01 = pack2(p0, p1);
            ull p23 = pack2(p2, p3);

            L01 = add2(L01, p01);
            L23 = add2(L23, p23);
            ull w01 = add2(VV0.x, EV0.x);
            ull w23 = add2(VV0.y, EV0.y);
            A01 = fma2(p01, w01, A01);
            A23 = fma2(p23, w23, A23);

            // rotate pipeline registers
            EA0 = EA1; EV0 = EV1;
            EA1 = EA2; EV1 = EV2;
            EA2 = EA3; EV2 = EV3;
            VV0 = VV1; VV1 = VV2;
            idx += 32;
        }

        float l0, l1, l2, l3, a0, a1, a2, a3;
        unpack2(L01, l0, l1);
        unpack2(L23, l2, l3);
        unpack2(A01, a0, a1);
        unpack2(A23, a2, a3);

        part[wid][lane][0] = l0;
        part[wid][lane][1] = l1;
        part[wid][lane][2] = l2;
        part[wid][lane][3] = l3;
        part[wid][lane][4] = a0;
        part[wid][lane][5] = a1;
        part[wid][lane][6] = a2;
        part[wid][lane][7] = a3;
    }
    __syncthreads();

    // ---- combine 4 partials per (r, f4) and write out ----
    if (wid < 4 && lane < 16) {
        const int r = wid;
        const int i = i0 + r;
        const int q = lane;
        float L[4], A[4];
#pragma unroll
        for (int c = 0; c < 4; c++) {
            L[c] = part[2 * r][q][c]      + part[2 * r][16 + q][c]
                 + part[2 * r + 1][q][c]  + part[2 * r + 1][16 + q][c];
            A[c] = part[2 * r][q][4 + c]     + part[2 * r][16 + q][4 + c]
                 + part[2 * r + 1][q][4 + c] + part[2 * r + 1][16 + q][4 + c];
        }
        float4 o;
        o.x = (L[0] > 0.f) ? A[0] / L[0] : 0.f;
        o.y = (L[1] > 0.f) ? A[1] / L[1] : 0.f;
        o.z = (L[2] > 0.f) ? A[2] / L[2] : 0.f;
        o.w = (L[3] > 0.f) ? A[3] / L[3] : 0.f;
        ((float4*)(out + (size_t)(b * N + i) * F))[q] = o;
    }
}

// ---------------------------------------------------------------------------
extern "C" void kernel_launch(void* const* d_in, const int* in_sizes, int n_in,
                              void* d_out, int out_size)
{
    const float*    h       = (const float*)d_in[0];
    const float*    e_att   = (const float*)d_in[1];
    const float*    e_value = (const float*)d_in[2];
    const uint32_t* mask    = (const uint32_t*)d_in[3];
    const float*    Wq      = (const float*)d_in[4];
    const float*    Wk      = (const float*)d_in[5];
    const float*    Wv      = (const float*)d_in[6];
    float*          out     = (float*)d_out;

    qkv_kernel<<<(B * N) / 4, 256>>>(h, Wq, Wk, Wv);
    attn_kernel<<<B * (N / RPC), 256>>>(e_att, e_value, mask, out);
}

// round 10
// speedup vs baseline: 1.2227x; 1.2227x over previous
#include <cuda_runtime.h>
#include <cstdint>

// Shapes (fixed by the problem)
#define B 8
#define N 256
#define IN 64
#define F 64          // H*D
#define H 8
#define D 8
#define RPC 2         // rows (i values) per CTA in the attention kernel

#define L2E 1.4426950408889634f
#define M2C (20.0f * 1.4426950408889634f)   // fixed softmax shift (log2 domain)

typedef unsigned long long ull;

// ---- packed f32x2 helpers (sm_103a FFMA2/FADD2 only reachable via PTX) ----
__device__ __forceinline__ ull pack2(float lo, float hi) {
    ull r; asm("mov.b64 %0, {%1, %2};" : "=l"(r) : "f"(lo), "f"(hi)); return r;
}
__device__ __forceinline__ void unpack2(ull v, float& lo, float& hi) {
    asm("mov.b64 {%0, %1}, %2;" : "=f"(lo), "=f"(hi) : "l"(v));
}
__device__ __forceinline__ ull fma2(ull a, ull b, ull c) {
    ull d; asm("fma.rn.f32x2 %0, %1, %2, %3;" : "=l"(d) : "l"(a), "l"(b), "l"(c)); return d;
}
__device__ __forceinline__ ull add2(ull a, ull b) {
    ull d; asm("add.rn.f32x2 %0, %1, %2;" : "=l"(d) : "l"(a), "l"(b)); return d;
}
__device__ __forceinline__ float ex2(float x) {
    float y; asm("ex2.approx.ftz.f32 %0, %1;" : "=f"(y) : "f"(x)); return y;
}

// Scratch (allocation-free rule: __device__ globals)
__device__ float g_Q[B * N * F];
__device__ float g_K[B * N * F];   // pre-scaled by D^-0.5
__device__ float g_V[B * N * F];

// ---------------------------------------------------------------------------
// Kernel A: Q/K/V projections.  grid = B*N/4 = 512 blocks, 256 threads.
// ---------------------------------------------------------------------------
__global__ void __launch_bounds__(256) qkv_kernel(
    const float* __restrict__ h,
    const float* __restrict__ Wq,
    const float* __restrict__ Wk,
    const float* __restrict__ Wv)
{
    __shared__ float hs[4][IN];
    int r   = threadIdx.x >> 6;    // 0..3
    int f   = threadIdx.x & 63;    // 0..63
    int row = blockIdx.x * 4 + r;

    hs[r][f] = h[row * IN + f];
    __syncthreads();

    float aq = 0.f, ak = 0.f, av = 0.f;
#pragma unroll
    for (int k = 0; k < IN; k++) {
        float hv = hs[r][k];
        aq = fmaf(hv, Wq[k * F + f], aq);
        ak = fmaf(hv, Wk[k * F + f], ak);
        av = fmaf(hv, Wv[k * F + f], av);
    }
    g_Q[row * F + f] = aq;
    g_K[row * F + f] = ak * 0.35355339059327373f;  // D^-0.5
    g_V[row * F + f] = av;
}

// ---------------------------------------------------------------------------
// Kernel B: fused qk + softmax(fixed-shift M=20, exact) + weighted sum.
// grid = B*(N/RPC) = 1024 blocks, 256 threads (8 warps), 4 CTAs/SM.
// Finer CTA granularity for wave balance: warp w handles row r = w&1,
// j-quarter jq = w>>1 (64 j's = 32 steps of 2).
// Lanes: jo = lane>>4 (which of 2 j's per step), q = lane&15 owns float4
// slice [4q,4q+4) of the f dim, h = q>>1.
// Inner loop identical in structure to the 55.9us R8 kernel (f32x2,
// depth-2 EA/EV prefetch, depth-1 VV, 64-reg cap).
// ---------------------------------------------------------------------------
__global__ void __launch_bounds__(256, 4) attn_kernel(
    const float* __restrict__ e_att,
    const float* __restrict__ e_value,
    const uint32_t* __restrict__ attn_mask,   // 4-byte elems; true <=> nonzero
    float* __restrict__ out)
{
    __shared__ float qk_s[RPC][N][H];    // 16 KB; qk*L2E - M2, or -1e30 masked
    __shared__ float q_s[RPC][F];        // 0.5 KB
    __shared__ float msk_s[RPC][N];      // 2 KB (phase-1 only)
    __shared__ float part[8][32][9];     // 9 KB (padded): l0..3, a0..3

    const int blk  = blockIdx.x;
    const int b    = blk >> 7;           // 128 blocks per batch
    const int i0   = (blk & 127) * RPC;
    const int tid  = threadIdx.x;
    const int wid  = tid >> 5;           // 0..7
    const int lane = tid & 31;

    // ---- load Q rows + mask into smem ----
    for (int t = tid; t < RPC * F; t += 256) {
        int r = t >> 6, f = t & 63;
        q_s[r][f] = g_Q[(b * N + i0 + r) * F + f];
    }
    for (int t = tid; t < RPC * N; t += 256) {
        int r = t >> 8, j = t & 255;
        msk_s[r][j] = (attn_mask[(b * N + i0 + r) * N + j] != 0u) ? 1.0f : 0.0f;
    }
    __syncthreads();

    // ---- phase 1: qk_s[r][j][h] = mask ? dot8*L2E - M2 : -1e30 ----
    {
        const int h  = lane >> 2;        // 0..7
        const int jm = lane & 3;         // 0..3
        float qreg[RPC][8];
#pragma unroll
        for (int r = 0; r < RPC; r++)
#pragma unroll
            for (int d = 0; d < 8; d++)
                qreg[r][d] = q_s[r][h * 8 + d];

        const float4* Kb = (const float4*)(g_K + b * N * F);
        for (int jg = wid * 8; jg < wid * 8 + 8; jg++) {
            int j = jm + 4 * jg;
            float4 k0 = Kb[j * 16 + h * 2];
            float4 k1 = Kb[j * 16 + h * 2 + 1];
#pragma unroll
            for (int r = 0; r < RPC; r++) {
                float s = qreg[r][0] * k0.x;
                s = fmaf(qreg[r][1], k0.y, s);
                s = fmaf(qreg[r][2], k0.z, s);
                s = fmaf(qreg[r][3], k0.w, s);
                s = fmaf(qreg[r][4], k1.x, s);
                s = fmaf(qreg[r][5], k1.y, s);
                s = fmaf(qreg[r][6], k1.z, s);
                s = fmaf(qreg[r][7], k1.w, s);
                qk_s[r][j][h] = (msk_s[r][j] != 0.0f) ? fmaf(s, L2E, -M2C)
                                                      : -1e30f;
            }
        }
    }
    __syncthreads();

    // ---- phase 3: streaming softmax + weighted accumulation (64-j slice) ----
    {
        const int r  = wid & 1;
        const int jq = wid >> 1;         // 0..3
        const int i  = i0 + r;
        const int jo = lane >> 4;        // 0/1
        const int q  = lane & 15;        // float4 index in f dim
        const int h  = q >> 1;
        const int j0 = jq * 64;

        const ulonglong2* pea = (const ulonglong2*)(e_att   + (size_t)(b * N + i) * N * F);
        const ulonglong2* pev = (const ulonglong2*)(e_value + (size_t)(b * N + i) * N * F);
        const ulonglong2* pV  = (const ulonglong2*)(g_V + b * N * F);

        const ull L2E2 = pack2(L2E, L2E);

        ull L01 = 0ull, L23 = 0ull, A01 = 0ull, A23 = 0ull;

        const int idx0   = (j0 + jo) * 16 + q;
        const int idxmax = idx0 + 31 * 32;

        // prime: slots k=0 (cur) and k=1 for EA/EV; k=0 for VV
        ulonglong2 EA0 = pea[idx0],      EV0 = pev[idx0];
        ulonglong2 EA1 = pea[idx0 + 32], EV1 = pev[idx0 + 32];
        ulonglong2 VV0 = pV[idx0];

        int idx = idx0;
#pragma unroll 2
        for (int k = 0; k < 32; k++) {
            // prefetch k+2 for DRAM streams, k+1 for V (clamped, in-bounds)
            int idp2 = idx + 64;  idp2 = (idp2 <= idxmax) ? idp2 : idxmax;
            int idp1 = idx + 32;  idp1 = (idp1 <= idxmax) ? idp1 : idxmax;
            ulonglong2 EA2 = pea[idp2];
            ulonglong2 EV2 = pev[idp2];
            ulonglong2 VV1 = pV[idp1];

            float qk  = qk_s[r][j0 + 2 * k + jo][h];
            ull   qk2 = pack2(qk, qk);

            ull t01 = fma2(EA0.x, L2E2, qk2);
            ull t23 = fma2(EA0.y, L2E2, qk2);
            float f0, f1, f2, f3;
            unpack2(t01, f0, f1);
            unpack2(t23, f2, f3);
            float p0 = ex2(f0), p1 = ex2(f1), p2 = ex2(f2), p3 = ex2(f3);
            ull p01 = pack2(p0, p1);
            ull p23 = pack2(p2, p3);

            L01 = add2(L01, p01);
            L23 = add2(L23, p23);
            ull w01 = add2(VV0.x, EV0.x);
            ull w23 = add2(VV0.y, EV0.y);
            A01 = fma2(p01, w01, A01);
            A23 = fma2(p23, w23, A23);

            // rotate pipeline registers
            EA0 = EA1; EV0 = EV1;
            EA1 = EA2; EV1 = EV2;
            VV0 = VV1;
            idx = idp1;
        }

        float l0, l1, l2, l3, a0, a1, a2, a3;
        unpack2(L01, l0, l1);
        unpack2(L23, l2, l3);
        unpack2(A01, a0, a1);
        unpack2(A23, a2, a3);

        part[wid][lane][0] = l0;
        part[wid][lane][1] = l1;
        part[wid][lane][2] = l2;
        part[wid][lane][3] = l3;
        part[wid][lane][4] = a0;
        part[wid][lane][5] = a1;
        part[wid][lane][6] = a2;
        part[wid][lane][7] = a3;
    }
    __syncthreads();

    // ---- combine 8 partials per (r, f4) and write out ----
    if (wid < RPC && lane < 16) {
        const int r = wid;            // row handled by this warp
        const int i = i0 + r;
        const int q = lane;
        float L[4] = {0, 0, 0, 0}, A[4] = {0, 0, 0, 0};
#pragma unroll
        for (int w = 0; w < 4; w++) {
            int ww = r + 2 * w;       // warps whose (w&1)==r
#pragma unroll
            for (int c = 0; c < 4; c++) {
                L[c] += part[ww][q][c]     + part[ww][16 + q][c];
                A[c] += part[ww][q][4 + c] + part[ww][16 + q][4 + c];
            }
        }
        float4 o;
        o.x = (L[0] > 0.f) ? A[0] / L[0] : 0.f;
        o.y = (L[1] > 0.f) ? A[1] / L[1] : 0.f;
        o.z = (L[2] > 0.f) ? A[2] / L[2] : 0.f;
        o.w = (L[3] > 0.f) ? A[3] / L[3] : 0.f;
        ((float4*)(out + (size_t)(b * N + i) * F))[q] = o;
    }
}

// ---------------------------------------------------------------------------
extern "C" void kernel_launch(void* const* d_in, const int* in_sizes, int n_in,
                              void* d_out, int out_size)
{
    const float*    h       = (const float*)d_in[0];
    const float*    e_att   = (const float*)d_in[1];
    const float*    e_value = (const float*)d_in[2];
    const uint32_t* mask    = (const uint32_t*)d_in[3];
    const float*    Wq      = (const float*)d_in[4];
    const float*    Wk      = (const float*)d_in[5];
    const float*    Wv      = (const float*)d_in[6];
    float*          out     = (float*)d_out;

    qkv_kernel<<<(B * N) / 4, 256>>>(h, Wq, Wk, Wv);
    attn_kernel<<<B * (N / RPC), 256>>>(e_att, e_value, mask, out);
}

// round 11
// speedup vs baseline: 1.3023x; 1.0651x over previous
#include <cuda_runtime.h>
#include <cstdint>

// Shapes (fixed by the problem)
#define B 8
#define N 256
#define IN 64
#define F 64          // H*D
#define H 8
#define D 8
#define RPC 2         // rows (i values) per attn item (CTA)
#define NPROD 128     // producer CTAs (qkv): 16 rows each -> 2048 rows

#define L2E 1.4426950408889634f
#define M2C (20.0f * 1.4426950408889634f)   // fixed softmax shift (log2 domain)

typedef unsigned long long ull;

// ---- packed f32x2 helpers (sm_103a FFMA2/FADD2 only reachable via PTX) ----
__device__ __forceinline__ ull pack2(float lo, float hi) {
    ull r; asm("mov.b64 %0, {%1, %2};" : "=l"(r) : "f"(lo), "f"(hi)); return r;
}
__device__ __forceinline__ void unpack2(ull v, float& lo, float& hi) {
    asm("mov.b64 {%0, %1}, %2;" : "=f"(lo), "=f"(hi) : "l"(v));
}
__device__ __forceinline__ ull fma2(ull a, ull b, ull c) {
    ull d; asm("fma.rn.f32x2 %0, %1, %2, %3;" : "=l"(d) : "l"(a), "l"(b), "l"(c)); return d;
}
__device__ __forceinline__ ull add2(ull a, ull b) {
    ull d; asm("add.rn.f32x2 %0, %1, %2;" : "=l"(d) : "l"(a), "l"(b)); return d;
}
__device__ __forceinline__ float ex2(float x) {
    float y; asm("ex2.approx.ftz.f32 %0, %1;" : "=f"(y) : "f"(x)); return y;
}
// streaming 16B load (evict-first at L1+L2)
__device__ __forceinline__ ulonglong2 ldcs2(const ulonglong2* p) {
    ulonglong2 v;
    asm("ld.global.cs.v2.u64 {%0, %1}, [%2];" : "=l"(v.x), "=l"(v.y) : "l"(p));
    return v;
}

// Scratch (allocation-free rule: __device__ globals)
__device__ float g_Q[B * N * F];
__device__ float g_K[B * N * F];   // pre-scaled by D^-0.5
__device__ float g_V[B * N * F];
__device__ int   g_done = 0;       // producers finished
__device__ int   g_fin  = 0;       // CTAs finished (for replay-safe reset)

// ---------------------------------------------------------------------------
// Fused kernel: producer (qkv) on CTAs 0..127, then all CTAs run attention.
// grid = 1024, 256 threads (8 warps), 4 CTAs/SM.
// Attn item = blk: b = blk>>7, i0 = (blk&127)*2.
// Warp w: row r = w&1, j-quarter jq = w>>1 (64 j's = 32 steps of 2).
// Lanes: jo = lane>>4, q = lane&15 owns float4 slice of f, h = q>>1.
// ---------------------------------------------------------------------------
__global__ void __launch_bounds__(256, 4) fused_kernel(
    const float* __restrict__ h,
    const float* __restrict__ e_att,
    const float* __restrict__ e_value,
    const uint32_t* __restrict__ attn_mask,   // 4-byte elems; true <=> nonzero
    const float* __restrict__ Wq,
    const float* __restrict__ Wk,
    const float* __restrict__ Wv,
    float* __restrict__ out)
{
    __shared__ float qk_s[RPC][N][H];    // 16 KB; qk*L2E - M2, or -1e30 masked
    __shared__ float q_s[RPC][F];        // 0.5 KB
    __shared__ float msk_s[RPC][N];      // 2 KB (phase-1 only)
    __shared__ float part[8][32][9];     // 9 KB (padded): l0..3, a0..3 (reused as hs)

    const int blk  = blockIdx.x;
    const int b    = blk >> 7;           // 128 items per batch
    const int i0   = (blk & 127) * RPC;
    const int tid  = threadIdx.x;
    const int wid  = tid >> 5;           // 0..7
    const int lane = tid & 31;

    // ================= producer: QKV projection (CTAs 0..127) ===============
    if (blk < NPROD) {
        float (*hs)[IN] = (float(*)[IN])&part[0][0][0];   // 16x64 = 4 KB, reused
        const int f    = tid & 63;
        const int rq   = tid >> 6;       // 0..3
        const int row0 = blk * 16;

        for (int t = tid; t < 16 * IN; t += 256)
            ((float*)hs)[t] = h[row0 * IN + t];
        __syncthreads();

        float aq[4] = {0, 0, 0, 0}, ak[4] = {0, 0, 0, 0}, av[4] = {0, 0, 0, 0};
#pragma unroll 8
        for (int k = 0; k < IN; k++) {
            float wq = Wq[k * F + f];
            float wk = Wk[k * F + f];
            float wv = Wv[k * F + f];
#pragma unroll
            for (int rr = 0; rr < 4; rr++) {
                float hv = hs[rq + 4 * rr][k];
                aq[rr] = fmaf(hv, wq, aq[rr]);
                ak[rr] = fmaf(hv, wk, ak[rr]);
                av[rr] = fmaf(hv, wv, av[rr]);
            }
        }
#pragma unroll
        for (int rr = 0; rr < 4; rr++) {
            int row = row0 + rq + 4 * rr;
            g_Q[row * F + f] = aq[rr];
            g_K[row * F + f] = ak[rr] * 0.35355339059327373f;  // D^-0.5
            g_V[row * F + f] = av[rr];
        }
        __threadfence();
        __syncthreads();
        if (tid == 0) atomicAdd(&g_done, 1);
    }

    // ---- mask load (independent of producer output) ----
    for (int t = tid; t < RPC * N; t += 256) {
        int r = t >> 8, j = t & 255;
        msk_s[r][j] = (attn_mask[(b * N + i0 + r) * N + j] != 0u) ? 1.0f : 0.0f;
    }

    // ---- wait for QKV ready ----
    if (tid == 0) {
        while (*(volatile int*)&g_done < NPROD) __nanosleep(64);
    }
    __syncthreads();
    __threadfence();   // order subsequent g_Q/g_K/g_V reads after the flag

    // ---- load Q rows into smem ----
    for (int t = tid; t < RPC * F; t += 256) {
        int r = t >> 6, f = t & 63;
        q_s[r][f] = g_Q[(b * N + i0 + r) * F + f];
    }
    __syncthreads();

    // ---- phase 1: qk_s[r][j][h] = mask ? dot8*L2E - M2 : -1e30 ----
    {
        const int hh = lane >> 2;        // 0..7
        const int jm = lane & 3;         // 0..3
        float qreg[RPC][8];
#pragma unroll
        for (int r = 0; r < RPC; r++)
#pragma unroll
            for (int d = 0; d < 8; d++)
                qreg[r][d] = q_s[r][hh * 8 + d];

        const float4* Kb = (const float4*)(g_K + b * N * F);
        for (int jg = wid * 8; jg < wid * 8 + 8; jg++) {
            int j = jm + 4 * jg;
            float4 k0 = Kb[j * 16 + hh * 2];
            float4 k1 = Kb[j * 16 + hh * 2 + 1];
#pragma unroll
            for (int r = 0; r < RPC; r++) {
                float s = qreg[r][0] * k0.x;
                s = fmaf(qreg[r][1], k0.y, s);
                s = fmaf(qreg[r][2], k0.z, s);
                s = fmaf(qreg[r][3], k0.w, s);
                s = fmaf(qreg[r][4], k1.x, s);
                s = fmaf(qreg[r][5], k1.y, s);
                s = fmaf(qreg[r][6], k1.z, s);
                s = fmaf(qreg[r][7], k1.w, s);
                qk_s[r][j][hh] = (msk_s[r][j] != 0.0f) ? fmaf(s, L2E, -M2C)
                                                       : -1e30f;
            }
        }
    }
    __syncthreads();

    // ---- phase 3: streaming softmax + weighted accumulation (64-j slice) ----
    {
        const int r  = wid & 1;
        const int jq = wid >> 1;         // 0..3
        const int i  = i0 + r;
        const int jo = lane >> 4;        // 0/1
        const int q  = lane & 15;        // float4 index in f dim
        const int hh = q >> 1;
        const int j0 = jq * 64;

        const ulonglong2* pea = (const ulonglong2*)(e_att   + (size_t)(b * N + i) * N * F);
        const ulonglong2* pev = (const ulonglong2*)(e_value + (size_t)(b * N + i) * N * F);
        const ulonglong2* pV  = (const ulonglong2*)(g_V + b * N * F);

        const ull L2E2 = pack2(L2E, L2E);

        ull L01 = 0ull, L23 = 0ull, A01 = 0ull, A23 = 0ull;

        const int idx0   = (j0 + jo) * 16 + q;
        const int idxmax = idx0 + 31 * 32;

        // prime: slots k=0 (cur) and k=1 for EA/EV; k=0 for VV
        ulonglong2 EA0 = ldcs2(pea + idx0),      EV0 = ldcs2(pev + idx0);
        ulonglong2 EA1 = ldcs2(pea + idx0 + 32), EV1 = ldcs2(pev + idx0 + 32);
        ulonglong2 VV0 = pV[idx0];

        int idx = idx0;
#pragma unroll 2
        for (int k = 0; k < 32; k++) {
            // prefetch k+2 for DRAM streams, k+1 for V (clamped, in-bounds)
            int idp2 = idx + 64;  idp2 = (idp2 <= idxmax) ? idp2 : idxmax;
            int idp1 = idx + 32;  idp1 = (idp1 <= idxmax) ? idp1 : idxmax;
            ulonglong2 EA2 = ldcs2(pea + idp2);
            ulonglong2 EV2 = ldcs2(pev + idp2);
            ulonglong2 VV1 = pV[idp1];

            float qk  = qk_s[r][j0 + 2 * k + jo][hh];
            ull   qk2 = pack2(qk, qk);

            ull t01 = fma2(EA0.x, L2E2, qk2);
            ull t23 = fma2(EA0.y, L2E2, qk2);
            float f0, f1, f2, f3;
            unpack2(t01, f0, f1);
            unpack2(t23, f2, f3);
            float p0 = ex2(f0), p1 = ex2(f1), p2 = ex2(f2), p3 = ex2(f3);
            ull p01 = pack2(p0, p1);
            ull p23 = pack2(p2, p3);

            L01 = add2(L01, p01);
            L23 = add2(L23, p23);
            ull w01 = add2(VV0.x, EV0.x);
            ull w23 = add2(VV0.y, EV0.y);
            A01 = fma2(p01, w01, A01);
            A23 = fma2(p23, w23, A23);

            // rotate pipeline registers
            EA0 = EA1; EV0 = EV1;
            EA1 = EA2; EV1 = EV2;
            VV0 = VV1;
            idx = idp1;
        }

        float l0, l1, l2, l3, a0, a1, a2, a3;
        unpack2(L01, l0, l1);
        unpack2(L23, l2, l3);
        unpack2(A01, a0, a1);
        unpack2(A23, a2, a3);

        part[wid][lane][0] = l0;
        part[wid][lane][1] = l1;
        part[wid][lane][2] = l2;
        part[wid][lane][3] = l3;
        part[wid][lane][4] = a0;
        part[wid][lane][5] = a1;
        part[wid][lane][6] = a2;
        part[wid][lane][7] = a3;
    }
    __syncthreads();

    // ---- combine 8 partials per (r, f4) and write out ----
    if (wid < RPC && lane < 16) {
        const int r = wid;
        const int i = i0 + r;
        const int q = lane;
        float L[4] = {0, 0, 0, 0}, A[4] = {0, 0, 0, 0};
#pragma unroll
        for (int w = 0; w < 4; w++) {
            int ww = r + 2 * w;          // warps whose (w&1)==r
#pragma unroll
            for (int c = 0; c < 4; c++) {
                L[c] += part[ww][q][c]     + part[ww][16 + q][c];
                A[c] += part[ww][q][4 + c] + part[ww][16 + q][4 + c];
            }
        }
        float4 o;
        o.x = (L[0] > 0.f) ? A[0] / L[0] : 0.f;
        o.y = (L[1] > 0.f) ? A[1] / L[1] : 0.f;
        o.z = (L[2] > 0.f) ? A[2] / L[2] : 0.f;
        o.w = (L[3] > 0.f) ? A[3] / L[3] : 0.f;
        ((float4*)(out + (size_t)(b * N + i) * F))[q] = o;
    }

    // ---- replay-safe reset of flags (last CTA to finish) ----
    __syncthreads();
    if (tid == 0) {
        int f = atomicAdd(&g_fin, 1);
        if (f == (B * (N / RPC)) - 1) {
            g_done = 0;
            g_fin  = 0;
            __threadfence();
        }
    }
}

// ---------------------------------------------------------------------------
extern "C" void kernel_launch(void* const* d_in, const int* in_sizes, int n_in,
                              void* d_out, int out_size)
{
    const float*    h       = (const float*)d_in[0];
    const float*    e_att   = (const float*)d_in[1];
    const float*    e_value = (const float*)d_in[2];
    const uint32_t* mask    = (const uint32_t*)d_in[3];
    const float*    Wq      = (const float*)d_in[4];
    const float*    Wk      = (const float*)d_in[5];
    const float*    Wv      = (const float*)d_in[6];
    float*          out     = (float*)d_out;

    fused_kernel<<<B * (N / RPC), 256>>>(h, e_att, e_value, mask, Wq, Wk, Wv, out);
}